// round 1
// baseline (speedup 1.0000x reference)
#include <cuda_runtime.h>

#define B_    8
#define C_    20
#define H_    512
#define W_    512
#define SH_   32
#define SW_   32
#define S_    1024
#define CELL_ 16
#define HW_   (H_*W_)
#define PSTR  260            // padded pixel-row stride (floats); 1040B = 16B-aligned
#define EPSV  1e-8f

// Scratch (device globals — no allocation allowed)
__device__ float g_seeds[B_][S_][C_];
__device__ float g_numer[B_][S_][C_];
__device__ float g_denom[B_][S_];

__constant__ int c_dy[9] = {-1,-1,-1, 0,0,0, 1,1,1};
__constant__ int c_dx[9] = {-1, 0, 1,-1,0,1,-1,0,1};

// ---------------------------------------------------------------------------
// K0: seed init = 16x16 mean pool per (b, cell, c); also zero numer/denom
// ---------------------------------------------------------------------------
__global__ void __launch_bounds__(256) k_init(const float* __restrict__ x)
{
    __shared__ __align__(16) float sX[C_][PSTR];
    const int b  = blockIdx.z, cy = blockIdx.y, cx = blockIdx.x;
    const int tid = threadIdx.x;
    const int ty = tid >> 4, tx = tid & 15;

    const float* xp = x + (size_t)b * C_ * HW_
                        + (size_t)(cy * CELL_ + ty) * W_ + (cx * CELL_ + tx);
#pragma unroll
    for (int c = 0; c < C_; c++) sX[c][tid] = xp[(size_t)c * HW_];
    __syncthreads();

    const int sidx = cy * SW_ + cx;
    if (tid < C_) {
        const float4* r = (const float4*)sX[tid];
        float a0 = 0.f, a1 = 0.f, a2 = 0.f, a3 = 0.f;
#pragma unroll
        for (int p = 0; p < 64; p++) {
            float4 v = r[p];
            a0 += v.x; a1 += v.y; a2 += v.z; a3 += v.w;
        }
        g_seeds[b][sidx][tid] = ((a0 + a1) + (a2 + a3)) * (1.f / 256.f);
        g_numer[b][sidx][tid] = 0.f;
    } else if (tid == C_) {
        g_denom[b][sidx] = 0.f;
    }
}

// ---------------------------------------------------------------------------
// Main kernel: one CTA per (b, cell). Phase A: logits + softmax per pixel.
// Phase B (accumulate iters): per-block GEMM reduction (9x21 outputs over 256
// pixels) + global atomics. FINAL: write Q to out, skip accumulation.
//
// logit[o] = 2*x.s_o - |s_o|^2   (|x|^2 cancels in softmax over o)
// ---------------------------------------------------------------------------
template<bool FINAL>
__global__ void __launch_bounds__(256) k_main(const float* __restrict__ x,
                                              float* __restrict__ out)
{
    __shared__ __align__(16) float sS[9][20];   // 2*seed, rows 80B (16B mult)
    __shared__ float sD0[9];                    // |seed|^2
    __shared__ int   sIdx[9];                   // clipped global seed index
    __shared__ __align__(16) float sXQ[30][PSTR]; // rows 0..19: X, 20: ones, 21..29: Q

    const int b  = blockIdx.z, cy = blockIdx.y, cx = blockIdx.x;
    const int tid = threadIdx.x;

    // Load 9x20 seed tile (pre-doubled) + neighbor indices
    if (tid < 180) {
        const int o = tid / 20, c = tid - o * 20;
        int iy = cy + c_dy[o]; iy = iy < 0 ? 0 : (iy > SH_ - 1 ? SH_ - 1 : iy);
        int ix = cx + c_dx[o]; ix = ix < 0 ? 0 : (ix > SW_ - 1 ? SW_ - 1 : ix);
        const int sidx = iy * SW_ + ix;
        if (c == 0) sIdx[o] = sidx;
        sS[o][c] = 2.f * g_seeds[b][sidx][c];
    }

    // Load this thread's pixel (all 20 channels) — coalesced, high MLP
    const int ty = tid >> 4, tx = tid & 15;
    const float* xp = x + (size_t)b * C_ * HW_
                        + (size_t)(cy * CELL_ + ty) * W_ + (cx * CELL_ + tx);
    float xv[C_];
#pragma unroll
    for (int c = 0; c < C_; c++) xv[c] = xp[(size_t)c * HW_];

    __syncthreads();

    // |s|^2 per offset (sS holds 2s -> 0.25 * sum(t^2))
    if (tid < 9) {
        float a = 0.f;
#pragma unroll
        for (int c = 0; c < C_; c++) a += sS[tid][c] * sS[tid][c];
        sD0[tid] = 0.25f * a;
    }

    if (!FINAL) {
        // Stash X tile + ones row for the reduction GEMM
#pragma unroll
        for (int c = 0; c < C_; c++) sXQ[c][tid] = xv[c];
        sXQ[20][tid] = 1.f;
    }
    __syncthreads();

    // Logits: 9 dot products of length 20, seeds via uniform float4 LDS
    float L[9];
#pragma unroll
    for (int o = 0; o < 9; o++) {
        const float4* s4 = (const float4*)sS[o];
        float a0 = 0.f, a1 = 0.f, a2 = 0.f, a3 = 0.f;
#pragma unroll
        for (int k = 0; k < 5; k++) {
            float4 t = s4[k];
            a0 = fmaf(t.x, xv[4*k+0], a0);
            a1 = fmaf(t.y, xv[4*k+1], a1);
            a2 = fmaf(t.z, xv[4*k+2], a2);
            a3 = fmaf(t.w, xv[4*k+3], a3);
        }
        L[o] = (a0 + a1) + (a2 + a3) - sD0[o];
    }

    // Softmax over the 9 offsets
    float m = L[0];
#pragma unroll
    for (int o = 1; o < 9; o++) m = fmaxf(m, L[o]);
    float e[9]; float sum = 0.f;
#pragma unroll
    for (int o = 0; o < 9; o++) { e[o] = __expf(L[o] - m); sum += e[o]; }
    const float inv = 1.f / sum;

    if (FINAL) {
        const int yy = cy * CELL_ + ty, xx = cx * CELL_ + tx;
        float* op = out + (size_t)b * 9 * HW_ + (size_t)yy * W_ + xx;
#pragma unroll
        for (int o = 0; o < 9; o++) op[(size_t)o * HW_] = e[o] * inv;
        return;
    }

#pragma unroll
    for (int o = 0; o < 9; o++) sXQ[21 + o][tid] = e[o] * inv;
    __syncthreads();

    // Reduction GEMM: 189 outputs (o,c) = sum_p Q[o][p] * X[c][p]
    // Mapping c = tid/9, o = tid%9 -> X reads are 4-chunk broadcasts (no
    // conflicts), Q reads are 9 chunks with <=2-way conflict.
    if (tid < 189) {
        const int c = tid / 9, o = tid - c * 9;
        const float4* Xr = (const float4*)sXQ[c];
        const float4* Qr = (const float4*)sXQ[21 + o];
        float a0 = 0.f, a1 = 0.f, a2 = 0.f, a3 = 0.f;
#pragma unroll 8
        for (int p = 0; p < 64; p++) {
            float4 xc = Xr[p];
            float4 qc = Qr[p];
            a0 = fmaf(xc.x, qc.x, a0);
            a1 = fmaf(xc.y, qc.y, a1);
            a2 = fmaf(xc.z, qc.z, a2);
            a3 = fmaf(xc.w, qc.w, a3);
        }
        const float v = (a0 + a1) + (a2 + a3);
        const int sidx = sIdx[o];
        if (c < 20) atomicAdd(&g_numer[b][sidx][c], v);
        else        atomicAdd(&g_denom[b][sidx], v);
    }
}

// ---------------------------------------------------------------------------
// Seed update: seeds = numer/(denom+eps); fused re-zero of numer/denom
// (lane 20 reads denom first, broadcast via shfl — no read-after-zero race)
// ---------------------------------------------------------------------------
__global__ void __launch_bounds__(32) k_update()
{
    const int bs = blockIdx.x;          // 0..8191
    const int b = bs >> 10, s = bs & 1023;
    const int l = threadIdx.x;

    float den = (l == 20) ? g_denom[b][s] : 0.f;
    den = __shfl_sync(0xffffffffu, den, 20);

    if (l < 20) {
        const float nu = g_numer[b][s][l];
        g_seeds[b][s][l] = nu / (den + EPSV);
        g_numer[b][s][l] = 0.f;
    } else if (l == 20) {
        g_denom[b][s] = 0.f;
    }
}

// ---------------------------------------------------------------------------
extern "C" void kernel_launch(void* const* d_in, const int* in_sizes, int n_in,
                              void* d_out, int out_size)
{
    const float* x = (const float*)d_in[0];
    float* out = (float*)d_out;

    dim3 grid(SW_, SH_, B_);

    k_init<<<grid, 256>>>(x);
    for (int it = 0; it < 3; it++) {
        k_main<false><<<grid, 256>>>(x, nullptr);
        k_update<<<8192, 32>>>();
    }
    k_main<true><<<grid, 256>>>(x, out);
}